// round 1
// baseline (speedup 1.0000x reference)
#include <cuda_runtime.h>
#include <math.h>
#include <float.h>

// Problem constants (from reference): B=8, Z=4, X=32, Y=32, N=4096
#define NPTS   4096
#define NB     8
#define THREADS 512
#define NWARP  (THREADS / 32)
#define MAXKEEP 128
#define CUT    2.0f

// Dynamic smem: 8 arrays of NPTS floats + warp scratch + kept arrays
#define SMEM_BYTES ((8 * NPTS + 2 * NWARP + 4 * MAXKEEP) * 4)

__device__ __forceinline__ float row_angle(float ax, float ay, float az,
                                           float bx, float by, float bz) {
    float na = sqrtf(ax * ax + ay * ay + az * az);
    float nb = sqrtf(bx * bx + by * by + bz * bz);
    float c = (ax * bx + ay * by + az * bz) / (na * nb);
    c = fminf(1.0f, fmaxf(-1.0f, c));
    return (acosf(c) / 3.14159265358979323846f) * 180.0f;
}

__global__ __launch_bounds__(THREADS, 1)
void mol_kernel(const float* __restrict__ pred,
                const float* __restrict__ targ,
                float* __restrict__ out) {
    extern __shared__ float sm[];
    float* s_conf = sm;                 // [NPTS] pred conf (raw, -FLT_MAX = inactive/suppressed)
    float* s_p0 = s_conf + NPTS;        // [NPTS] pred pos normalized (z,x,y comps)
    float* s_p1 = s_p0 + NPTS;
    float* s_p2 = s_p1 + NPTS;
    float* s_t0 = s_p2 + NPTS;          // [NPTS] target pos in REAL coords
    float* s_t1 = s_t0 + NPTS;
    float* s_t2 = s_t1 + NPTS;
    float* s_tc = s_t2 + NPTS;          // [NPTS] target conf
    float* wv = s_tc + NPTS;            // [NWARP] warp partial values
    int* wi = (int*)(wv + NWARP);       // [NWARP] warp partial indices
    float* kx = (float*)(wi + NWARP);   // kept point normalized coords
    float* ky = kx + MAXKEEP;
    float* kz = ky + MAXKEEP;
    int* kid = (int*)(kz + MAXKEEP);    // kept original indices

    __shared__ int sK, sSel, sTP, sNTG;
    __shared__ float sAng;
    __shared__ float selp[3];

    const int tid = threadIdx.x;
    const int lane = tid & 31;
    const int warp = tid >> 5;
    const int b = blockIdx.x;
    const float* P = pred + (long long)b * NPTS * 10;
    const float* T = targ + (long long)b * NPTS * 10;

    // ---- Phase 1: stage conf + positions in smem ----
    for (int n = tid; n < NPTS; n += THREADS) {
        const float* p = P + n * 10;
        const float* t = T + n * 10;
        float c = p[0];
        int z = n >> 10, x = (n >> 5) & 31, y = n & 31;
        // sigmoid(c) > 0.5  <=>  c > 0  (exact)
        s_conf[n] = (c > 0.0f) ? c : -FLT_MAX;
        // normalized pos: (offset + cell)/ZXY ; /4 and /32 are exact pow2 mults
        s_p0[n] = (p[1] + (float)z) * 0.25f;
        s_p1[n] = (p[2] + (float)x) * 0.03125f;
        s_p2[n] = (p[3] + (float)y) * 0.03125f;
        // target: real coords = normalized * REAL_SIZE(25,25,4)
        s_tc[n] = t[0];
        s_t0[n] = ((t[1] + (float)z) * 0.25f) * 25.0f;
        s_t1[n] = ((t[2] + (float)x) * 0.03125f) * 25.0f;
        s_t2[n] = ((t[3] + (float)y) * 0.03125f) * 4.0f;
    }
    if (tid == 0) { sK = 0; sTP = 0; sAng = 0.0f; }
    __syncthreads();

    // ---- Phase 2: round-based greedy NMS (== converged iterative suppression) ----
    for (;;) {
        // block argmax over remaining confidence (tie -> lowest index)
        float bv = -FLT_MAX;
        int bi = 0x7fffffff;
        for (int n = tid; n < NPTS; n += THREADS) {
            float v = s_conf[n];
            if (v > bv) { bv = v; bi = n; }   // ascending n => ties keep lowest idx
        }
        #pragma unroll
        for (int o = 16; o; o >>= 1) {
            float v2 = __shfl_down_sync(0xffffffffu, bv, o);
            int i2 = __shfl_down_sync(0xffffffffu, bi, o);
            if (v2 > bv || (v2 == bv && i2 < bi)) { bv = v2; bi = i2; }
        }
        if (lane == 0) { wv[warp] = bv; wi[warp] = bi; }
        __syncthreads();
        if (warp == 0) {
            float v = (lane < NWARP) ? wv[lane] : -FLT_MAX;
            int i = (lane < NWARP) ? wi[lane] : 0x7fffffff;
            #pragma unroll
            for (int o = 16; o; o >>= 1) {
                float v2 = __shfl_down_sync(0xffffffffu, v, o);
                int i2 = __shfl_down_sync(0xffffffffu, i, o);
                if (v2 > v || (v2 == v && i2 < i)) { v = v2; i = i2; }
            }
            if (lane == 0) {
                if (v == -FLT_MAX || sK >= MAXKEEP) {
                    sSel = -1;
                } else {
                    sSel = i;
                    int K = sK;
                    kx[K] = s_p0[i]; ky[K] = s_p1[i]; kz[K] = s_p2[i]; kid[K] = i;
                    selp[0] = s_p0[i]; selp[1] = s_p1[i]; selp[2] = s_p2[i];
                    sK = K + 1;
                }
            }
        }
        __syncthreads();
        if (sSel < 0) break;
        // suppress everything within CUT of selected (includes itself, d=0)
        float c0 = selp[0], c1 = selp[1], c2 = selp[2];
        for (int n = tid; n < NPTS; n += THREADS) {
            if (s_conf[n] != -FLT_MAX) {
                float d0 = s_p0[n] - c0, d1 = s_p1[n] - c1, d2 = s_p2[n] - c2;
                float ss = (d0 * d0 + d1 * d1) + d2 * d2;
                if (sqrtf(ss) < CUT) s_conf[n] = -FLT_MAX;
            }
        }
        __syncthreads();
    }

    // ---- Phase 3a: count active targets ----
    {
        int cnt = 0;
        for (int n = tid; n < NPTS; n += THREADS) cnt += (s_tc[n] > 0.5f) ? 1 : 0;
        #pragma unroll
        for (int o = 16; o; o >>= 1) cnt += __shfl_down_sync(0xffffffffu, cnt, o);
        if (lane == 0) wi[warp] = cnt;
        __syncthreads();
        if (tid == 0) {
            int s = 0;
            for (int w = 0; w < NWARP; w++) s += wi[w];
            sNTG = s;
        }
        __syncthreads();
    }

    // ---- Phase 3b: per kept pred, find first in-range active target; angles ----
    const int K = sK;
    for (int k = 0; k < K; k++) {
        float q0 = kx[k] * 25.0f, q1 = ky[k] * 25.0f, q2 = kz[k] * 4.0f;
        int best = 0x7fffffff;
        for (int t = tid; t < NPTS; t += THREADS) {
            if (s_tc[t] > 0.5f) {
                float d0 = s_t0[t] - q0, d1 = s_t1[t] - q1, d2 = s_t2[t] - q2;
                float ss = (d0 * d0 + d1 * d1) + d2 * d2;
                if (sqrtf(ss) < CUT && t < best) best = t;
            }
        }
        #pragma unroll
        for (int o = 16; o; o >>= 1) {
            int v2 = __shfl_down_sync(0xffffffffu, best, o);
            if (v2 < best) best = v2;
        }
        if (lane == 0) wi[warp] = best;
        __syncthreads();
        if (tid == 0) {
            int bmin = 0x7fffffff;
            for (int w = 0; w < NWARP; w++) if (wi[w] < bmin) bmin = wi[w];
            if (bmin != 0x7fffffff) {
                sTP += 1;
                int i = kid[k];
                const float* p = P + (long long)i * 10;
                const float* t = T + (long long)bmin * 10;
                float ax = p[4], ay = p[5], az = p[6];
                float bx = p[7], by = p[8], bz = p[9];
                float cx = ay * bz - az * by;
                float cy = az * bx - ax * bz;
                float cz = ax * by - ay * bx;
                float tax = t[4], tay = t[5], taz = t[6];
                float tbx = t[7], tby = t[8], tbz = t[9];
                float tcx = tay * tbz - taz * tby;
                float tcy = taz * tbx - tax * tbz;
                float tcz = tax * tby - tay * tbx;
                sAng += row_angle(ax, ay, az, tax, tay, taz)
                      + row_angle(bx, by, bz, tbx, tby, tbz)
                      + row_angle(cx, cy, cz, tcx, tcy, tcz);
            }
        }
        __syncthreads();
    }

    // ---- Phase 4: write outputs ----
    // layout: out[0:24] = cm[B][3] (tp, n_pd - tp, n_tg - tp), out[24:32] = ms[B]
    if (tid == 0) {
        float tp = (float)sTP;
        out[b * 3 + 0] = tp;
        out[b * 3 + 1] = (float)K - tp;
        out[b * 3 + 2] = (float)sNTG - tp;
        out[3 * NB + b] = (sTP > 0) ? (sAng / (3.0f * tp)) : 0.0f;
    }
}

extern "C" void kernel_launch(void* const* d_in, const int* in_sizes, int n_in,
                              void* d_out, int out_size) {
    const float* pred = (const float*)d_in[0];
    const float* targ = (const float*)d_in[1];
    float* out = (float*)d_out;
    cudaFuncSetAttribute(mol_kernel, cudaFuncAttributeMaxDynamicSharedMemorySize,
                         SMEM_BYTES);
    mol_kernel<<<NB, THREADS, SMEM_BYTES>>>(pred, targ, out);
}